// round 1
// baseline (speedup 1.0000x reference)
#include <cuda_runtime.h>

// PrefixSumCounts: counts[b,s] = #{t <= s : x[b,t] == x[b,s]}
// B=4, S=4096, V=32000 (fixed by the problem instance).
//
// Decomposition: C=16 chunks of L=256 per row.
//   Z: zero dense per-chunk histograms g_cnt[B][C][VS]
//   H: per-(b,c) block -> within-chunk inclusive rank (SMEM scan) + hist atomics
//   F: per-position -> add sum of earlier-chunk histogram cells (L2 lookups)

#define BB 4
#define SS 4096
#define CC 16
#define LL 256            // SS/CC
#define VSHIFT 15
#define VS (1 << VSHIFT)  // 32768 >= vocab 32000

__device__ int g_cnt[BB * CC * VS];  // 8.4 MB static scratch (zero-init at load)

__global__ void zero_kernel() {
    int i = blockIdx.x * blockDim.x + threadIdx.x;
    reinterpret_cast<int4*>(g_cnt)[i] = make_int4(0, 0, 0, 0);
}

__global__ void rank_hist_kernel(const int* __restrict__ x, float* __restrict__ out) {
    __shared__ int xs[LL];
    const int c = blockIdx.x;
    const int b = blockIdx.y;
    const int t = threadIdx.x;
    const int gpos = b * SS + c * LL + t;

    const int v = x[gpos];
    xs[t] = v;
    __syncthreads();

    // Inclusive rank of position t among equal values within this chunk.
    int rank = 0;
#pragma unroll 4
    for (int j = 0; j < t; ++j) {
        rank += (xs[j] == v);
    }
    out[gpos] = (float)(rank + 1);

    // Per-chunk histogram (spread addresses; 16K atomics total).
    atomicAdd(&g_cnt[((b * CC + c) << VSHIFT) + v], 1);
}

__global__ void add_base_kernel(const int* __restrict__ x, float* __restrict__ out) {
    const int idx = blockIdx.x * blockDim.x + threadIdx.x;  // 0 .. B*S-1
    const int b = idx / SS;
    const int s = idx - b * SS;
    const int c = s / LL;
    const int v = x[idx];

    const int* base_ptr = &g_cnt[(b * CC) << VSHIFT] + v;
    int base = 0;
    // 15 predicated, fully independent LDGs -> deep MLP, all L2 hits.
#pragma unroll
    for (int cp = 0; cp < CC - 1; ++cp) {
        if (cp < c) base += base_ptr[cp << VSHIFT];
    }
    out[idx] += (float)base;
}

extern "C" void kernel_launch(void* const* d_in, const int* in_sizes, int n_in,
                              void* d_out, int out_size) {
    (void)in_sizes; (void)n_in; (void)out_size;
    const int* x = (const int*)d_in[0];
    float* out = (float*)d_out;

    // 8.4MB / 16B per thread = 524288 threads = 2048 blocks x 256
    zero_kernel<<<(BB * CC * VS) / 4 / 256, 256>>>();
    rank_hist_kernel<<<dim3(CC, BB), LL>>>(x, out);
    add_base_kernel<<<(BB * SS) / 256, 256>>>(x, out);
}

// round 2
// speedup vs baseline: 1.0086x; 1.0086x over previous
#include <cuda_runtime.h>

// PrefixSumCounts: counts[b,s] = #{t <= s : x[b,t] == x[b,s]}
// B=4, S=4096, V=32000 (fixed by this problem instance).
//
// Single fused kernel, 64 blocks (= B*C, all co-resident in wave 1):
//   phase 1: per-(b,c) block: within-chunk inclusive rank (SMEM scan)
//            + per-chunk histogram atomics into g_cnt[b][c][v]
//   grid barrier (software, L2 atomic; safe: grid < #SMs)
//   phase 2: out[pos] = rank + 1 + sum over earlier chunks' g_cnt[b][cp][v]
//   grid barrier
//   phase 3: cleanup — zero exactly the touched cells so g_cnt and the
//            barrier counter return to initial state for the next graph replay.

#define BB 4
#define SS 4096
#define CC 16
#define LL 256            // SS / CC
#define VSHIFT 15
#define VS (1 << VSHIFT)  // 32768 >= vocab 32000
#define NBLK (BB * CC)    // 64

__device__ int g_cnt[BB * CC * VS];   // zero at module load; restored each launch
__device__ unsigned int g_bar;        // zero at load; restored each launch

__device__ __forceinline__ void grid_barrier(unsigned int target) {
    __syncthreads();
    if (threadIdx.x == 0) {
        __threadfence();
        atomicAdd(&g_bar, 1u);
        volatile unsigned int* p = &g_bar;
        while (*p < target) { }
        __threadfence();
    }
    __syncthreads();
}

__global__ void __launch_bounds__(LL, 1) fused_counts_kernel(
    const int* __restrict__ x, float* __restrict__ out)
{
    __shared__ int xs[LL];
    const int c = blockIdx.x & (CC - 1);
    const int b = blockIdx.x >> 4;     // gridDim.x == BB*CC == 64
    const int t = threadIdx.x;
    const int gpos = b * SS + c * LL + t;

    // ---- phase 1: within-chunk rank + per-chunk histogram ----
    const int v = __ldg(&x[gpos]);
    xs[t] = v;
    __syncthreads();

    int rank = 0;
#pragma unroll 4
    for (int j = 0; j < t; ++j) {
        rank += (xs[j] == v);
    }

    const int cell = ((b * CC + c) << VSHIFT) + v;
    atomicAdd(&g_cnt[cell], 1);

    // ---- barrier 1: all histograms complete ----
    grid_barrier(NBLK);

    // ---- phase 2: add counts from earlier chunks (15 independent L2 loads) ----
    const int* base_ptr = &g_cnt[(b * CC) << VSHIFT] + v;
    int base = 0;
#pragma unroll
    for (int cp = 0; cp < CC - 1; ++cp) {
        if (cp < c) base += __ldcg(&base_ptr[cp << VSHIFT]);
    }
    out[gpos] = (float)(rank + 1 + base);

    // ---- barrier 2: all reads of g_cnt complete ----
    grid_barrier(2 * NBLK);

    // ---- phase 3: cleanup touched cells; last arriver resets the barrier ----
    g_cnt[cell] = 0;   // redundant stores across equal values are fine

    __syncthreads();
    if (threadIdx.x == 0) {
        __threadfence();
        unsigned int old = atomicAdd(&g_bar, 1u);
        if (old == 3u * NBLK - 1u) {
            g_bar = 0u;   // last block resets; kernel completion orders this
        }
    }
}

extern "C" void kernel_launch(void* const* d_in, const int* in_sizes, int n_in,
                              void* d_out, int out_size) {
    (void)in_sizes; (void)n_in; (void)out_size;
    const int* x = (const int*)d_in[0];
    float* out = (float*)d_out;
    fused_counts_kernel<<<NBLK, LL>>>(x, out);
}